// round 12
// baseline (speedup 1.0000x reference)
#include <cuda_runtime.h>

#define NN 50000
#define NE 600000
#define HID 128
#define TILE_N 64
#define KCH 32
#define SCAN_B 1024
#define NBLK ((NN + SCAN_B - 1) / SCAN_B)   // 49 scan blocks

typedef unsigned long long u64;

// Scratch (static device globals — no runtime allocation).
__device__ __align__(256) float g_q[(size_t)NN * HID];
__device__ __align__(256) float g_k[(size_t)NN * HID];
__device__ __align__(256) float g_v[(size_t)NN * HID];
__device__ __align__(256) float g_WT[3 * HID * HID];
__device__ __align__(256) int   g_src[NE];
__device__ __align__(256) int   g_dst[NE];
__device__ __align__(256) int   g_count[NN];
__device__ __align__(256) int   g_start[NN + 1];
__device__ __align__(256) int   g_cursor[NN];
__device__ __align__(256) int2  g_es[NE];        // (edge id, src) sorted by dst
__device__ __align__(256) int   g_bsum[NBLK];
__device__ __align__(256) int   g_boff[NBLK];
__device__ int g_is_i32;

// ---------------------------------------------------------------------------
// f32x2 packed-FMA helpers (FFMA2 — PTX-only, exact fp32).
// ---------------------------------------------------------------------------
__device__ __forceinline__ u64 pack2(float lo, float hi) {
    u64 r; asm("mov.b64 %0, {%1, %2};" : "=l"(r) : "f"(lo), "f"(hi)); return r;
}
__device__ __forceinline__ void fma2(u64& acc, u64 a, u64 b) {
    asm("fma.rn.f32x2 %0, %1, %2, %0;" : "+l"(acc) : "l"(a), "l"(b));
}
__device__ __forceinline__ float merge2(u64 v) {
    float lo, hi;
    asm("mov.b64 {%0, %1}, %2;" : "=f"(lo), "=f"(hi) : "l"(v));
    return lo + hi;
}

// ---------------------------------------------------------------------------
// Kernel Z: zero counters + dtype flag + detection in one pass.
// ---------------------------------------------------------------------------
__global__ void zero_and_detect(const unsigned int* __restrict__ ei_words) {
    int t = blockIdx.x * blockDim.x + threadIdx.x;
    if (t == 0) g_is_i32 = 0;
    for (int i = t; i < NN; i += blockDim.x * gridDim.x) g_count[i] = 0;
    unsigned int acc = 0;
    for (int i = t; i < NE; i += blockDim.x * gridDim.x)
        acc |= ei_words[2 * i + 1];
    if (acc) atomicOr(&g_is_i32, 1);
}

// ---------------------------------------------------------------------------
// Kernel B: decode edge_index into g_src/g_dst AND histogram dst degrees.
// ---------------------------------------------------------------------------
__global__ void convert_idx(const unsigned int* __restrict__ ei_words) {
    int t = blockIdx.x * blockDim.x + threadIdx.x;
    int i32 = g_is_i32;
    for (int e = t; e < NE; e += blockDim.x * gridDim.x) {
        int s, d;
        if (i32) {
            s = (int)ei_words[e];
            d = (int)ei_words[NE + e];
        } else {
            s = (int)ei_words[2 * (size_t)e];
            d = (int)ei_words[2 * ((size_t)NE + e)];
        }
        g_src[e] = s;
        g_dst[e] = d;
        atomicAdd(&g_count[d], 1);
    }
}

// ---------------------------------------------------------------------------
// 3-phase parallel scan.
// ---------------------------------------------------------------------------
__global__ __launch_bounds__(SCAN_B) void scan_phase1() {
    __shared__ int ps[SCAN_B];
    int tid = threadIdx.x;
    int idx = blockIdx.x * SCAN_B + tid;
    int val = (idx < NN) ? g_count[idx] : 0;
    ps[tid] = val;
    __syncthreads();
#pragma unroll
    for (int d = 1; d < SCAN_B; d <<= 1) {
        int v = (tid >= d) ? ps[tid - d] : 0;
        __syncthreads();
        ps[tid] += v;
        __syncthreads();
    }
    if (idx < NN) g_start[idx] = ps[tid] - val;
    if (tid == SCAN_B - 1) g_bsum[blockIdx.x] = ps[tid];
}

__global__ void scan_phase2() {
    int l = threadIdx.x;             // 64 threads, NBLK=49 <= 64
    int v = (l < NBLK) ? g_bsum[l] : 0;
    int orig = v;
    __shared__ int s[64];
    s[l] = v;
    __syncthreads();
#pragma unroll
    for (int d = 1; d < 64; d <<= 1) {
        int t = (l >= d) ? s[l - d] : 0;
        __syncthreads();
        s[l] += t;
        __syncthreads();
    }
    if (l < NBLK) g_boff[l] = s[l] - orig;
    if (l == 63) g_start[NN] = s[63];
}

__global__ __launch_bounds__(SCAN_B) void scan_phase3() {
    int idx = blockIdx.x * SCAN_B + threadIdx.x;
    if (idx < NN) {
        int v = g_start[idx] + g_boff[blockIdx.x];
        g_start[idx] = v;
        g_cursor[idx] = v;
    }
}

// ---------------------------------------------------------------------------
// Kernel D: permute (edge id, src) pairs into dst-sorted order.
// ---------------------------------------------------------------------------
__global__ void permute_idx() {
    int t = blockIdx.x * blockDim.x + threadIdx.x;
    for (int e = t; e < NE; e += blockDim.x * gridDim.x) {
        int d = g_dst[e];
        int pos = atomicAdd(&g_cursor[d], 1);
        g_es[pos] = make_int2(e, g_src[e]);
    }
}

// ---------------------------------------------------------------------------
// Kernel 0: transpose the three 128x128 weight matrices (tiny).
// ---------------------------------------------------------------------------
__global__ void transpose_w(const float* __restrict__ Wq,
                            const float* __restrict__ Wk,
                            const float* __restrict__ Wv) {
    int t = blockIdx.x * blockDim.x + threadIdx.x;
    int total = 3 * HID * HID;
    for (int idx = t; idx < total; idx += blockDim.x * gridDim.x) {
        int m = idx / (HID * HID);
        int r = idx - m * (HID * HID);
        int o = r >> 7;
        int d = r & 127;
        const float* W = (m == 0) ? Wq : (m == 1) ? Wk : Wv;
        g_WT[m * HID * HID + d * HID + o] = W[o * HID + d];
    }
}

// ---------------------------------------------------------------------------
// Kernel 1: QKV GEMM, FFMA2 with d-pair accumulators.
// c2[n][o] is f32x2 = (sum over even d, sum over odd d) for output o;
// merged by one FADD at the end. a-operand = ld.shared.b64 of xs[n][d,d+1]
// (no packing!), b-operand = (w_d[o], w_{d+1}[o]) packed ONCE per d4 and
// reused by all 8 nodes (8 packs/d4 vs 32 before). This removes the ALU-pipe
// MOV flood that made FFMA2 issue-neutral in R5-R11.
// ---------------------------------------------------------------------------
__global__ __launch_bounds__(256, 2) void qkv_gemm(const float* __restrict__ x,
                                                   int m_base) {
    __shared__ float wt[KCH][HID];
    __shared__ float xs[TILE_N][KCH];

    int m = blockIdx.y + m_base;
    const float* wtg = &g_WT[m * HID * HID];
    float* out = (m == 0) ? g_q : (m == 1) ? g_k : g_v;

    int node0 = blockIdx.x * TILE_N;
    int tid = threadIdx.x;
    int w = tid >> 5;
    int l = tid & 31;

    const float4* xg4 = (const float4*)x;
    int xn0 = tid >> 3,         xc0 = tid & 7;
    int xn1 = (tid + 256) >> 3, xc1 = (tid + 256) & 7;
    int gn0 = node0 + xn0, gn1 = node0 + xn1;

    u64 c2[8][4];
#pragma unroll
    for (int n = 0; n < 8; n++)
#pragma unroll
        for (int o = 0; o < 4; o++) c2[n][o] = 0ull;

#pragma unroll
    for (int kk = 0; kk < HID / KCH; kk++) {
        int k0 = kk * KCH;
        if (kk) __syncthreads();
        {
            float4* wt4 = (float4*)&wt[0][0];
            const float4* srcw = (const float4*)&wtg[(size_t)k0 * HID];
#pragma unroll
            for (int i = 0; i < 4; i++)
                wt4[tid + i * 256] = srcw[tid + i * 256];
        }
        {
            float4* xs4 = (float4*)&xs[0][0];
            xs4[tid] = (gn0 < NN) ? xg4[(size_t)gn0 * 32 + (k0 >> 2) + xc0]
                                  : make_float4(0.f, 0.f, 0.f, 0.f);
            xs4[tid + 256] = (gn1 < NN) ? xg4[(size_t)gn1 * 32 + (k0 >> 2) + xc1]
                                        : make_float4(0.f, 0.f, 0.f, 0.f);
        }
        __syncthreads();

#pragma unroll
        for (int d4 = 0; d4 < KCH / 4; d4++) {
            int d = d4 * 4;
            float4 w0 = *(float4*)&wt[d + 0][4 * l];
            float4 w1 = *(float4*)&wt[d + 1][4 * l];
            float4 w2 = *(float4*)&wt[d + 2][4 * l];
            float4 w3 = *(float4*)&wt[d + 3][4 * l];
            // 8 packs per d4, shared by all 8 nodes below.
            u64 wp01[4], wp23[4];
            wp01[0] = pack2(w0.x, w1.x); wp23[0] = pack2(w2.x, w3.x);
            wp01[1] = pack2(w0.y, w1.y); wp23[1] = pack2(w2.y, w3.y);
            wp01[2] = pack2(w0.z, w1.z); wp23[2] = pack2(w2.z, w3.z);
            wp01[3] = pack2(w0.w, w1.w); wp23[3] = pack2(w2.w, w3.w);
#pragma unroll
            for (int n = 0; n < 8; n++) {
                const u64* xp = (const u64*)&xs[8 * w + n][d];
                u64 x01 = xp[0];   // (x_d, x_{d+1}) — direct LDS.64, no pack
                u64 x23 = xp[1];   // (x_{d+2}, x_{d+3})
                fma2(c2[n][0], x01, wp01[0]); fma2(c2[n][0], x23, wp23[0]);
                fma2(c2[n][1], x01, wp01[1]); fma2(c2[n][1], x23, wp23[1]);
                fma2(c2[n][2], x01, wp01[2]); fma2(c2[n][2], x23, wp23[2]);
                fma2(c2[n][3], x01, wp01[3]); fma2(c2[n][3], x23, wp23[3]);
            }
        }
    }

#pragma unroll
    for (int n = 0; n < 8; n++) {
        int gn = node0 + 8 * w + n;
        if (gn < NN) {
            float4 r;
            r.x = merge2(c2[n][0]);
            r.y = merge2(c2[n][1]);
            r.z = merge2(c2[n][2]);
            r.w = merge2(c2[n][3]);
            *(float4*)&out[(size_t)gn * HID + 4 * l] = r;
        }
    }
}

// ---------------------------------------------------------------------------
// Kernel 2: FUSED dst-sorted edge kernel. One warp per dst node.
// q loaded once per node; per edge: k,v gathers (L2-resident), w_ij 512B
// coalesced row (__ldcs stream), cutoff scalar. Unroll 4 -> 12 LDG.128 in
// flight. Alpha in-register via quad shfl-reduce; no atomics.
// ---------------------------------------------------------------------------
__global__ __launch_bounds__(256) void edge_fused(
    const float* __restrict__ w_ij,
    const float* __restrict__ cutoff,
    float* __restrict__ out) {

    int node = (blockIdx.x * blockDim.x + threadIdx.x) >> 5;
    int l = threadIdx.x & 31;
    if (node >= NN) return;

    int p     = g_start[node];
    int e_end = g_start[node + 1];

    float4 q = *(const float4*)&g_q[(size_t)node * HID + 4 * l];
    float4 acc = make_float4(0.f, 0.f, 0.f, 0.f);

    for (; p + 4 <= e_end; p += 4) {
        int2 es0 = g_es[p];
        int2 es1 = g_es[p + 1];
        int2 es2 = g_es[p + 2];
        int2 es3 = g_es[p + 3];

        float4 k0 = *(const float4*)&g_k[(size_t)es0.y * HID + 4 * l];
        float4 k1 = *(const float4*)&g_k[(size_t)es1.y * HID + 4 * l];
        float4 k2 = *(const float4*)&g_k[(size_t)es2.y * HID + 4 * l];
        float4 k3 = *(const float4*)&g_k[(size_t)es3.y * HID + 4 * l];
        float4 v0 = *(const float4*)&g_v[(size_t)es0.y * HID + 4 * l];
        float4 v1 = *(const float4*)&g_v[(size_t)es1.y * HID + 4 * l];
        float4 v2 = *(const float4*)&g_v[(size_t)es2.y * HID + 4 * l];
        float4 v3 = *(const float4*)&g_v[(size_t)es3.y * HID + 4 * l];
        float4 w0 = __ldcs((const float4*)&w_ij[(size_t)es0.x * HID + 4 * l]);
        float4 w1 = __ldcs((const float4*)&w_ij[(size_t)es1.x * HID + 4 * l]);
        float4 w2 = __ldcs((const float4*)&w_ij[(size_t)es2.x * HID + 4 * l]);
        float4 w3 = __ldcs((const float4*)&w_ij[(size_t)es3.x * HID + 4 * l]);
        float  c0 = __ldg(&cutoff[es0.x]);
        float  c1 = __ldg(&cutoff[es1.x]);
        float  c2 = __ldg(&cutoff[es2.x]);
        float  c3 = __ldg(&cutoff[es3.x]);

        float p0 = q.x * w0.x * k0.x + q.y * w0.y * k0.y + q.z * w0.z * k0.z + q.w * w0.w * k0.w;
        float p1 = q.x * w1.x * k1.x + q.y * w1.y * k1.y + q.z * w1.z * k1.z + q.w * w1.w * k1.w;
        float p2 = q.x * w2.x * k2.x + q.y * w2.y * k2.y + q.z * w2.z * k2.z + q.w * w2.w * k2.w;
        float p3 = q.x * w3.x * k3.x + q.y * w3.y * k3.y + q.z * w3.z * k3.z + q.w * w3.w * k3.w;

        p0 += __shfl_xor_sync(0xffffffffu, p0, 1);
        p0 += __shfl_xor_sync(0xffffffffu, p0, 2);
        p1 += __shfl_xor_sync(0xffffffffu, p1, 1);
        p1 += __shfl_xor_sync(0xffffffffu, p1, 2);
        p2 += __shfl_xor_sync(0xffffffffu, p2, 1);
        p2 += __shfl_xor_sync(0xffffffffu, p2, 2);
        p3 += __shfl_xor_sync(0xffffffffu, p3, 1);
        p3 += __shfl_xor_sync(0xffffffffu, p3, 2);

        float a0 = p0 * 0.25f * c0;
        float a1 = p1 * 0.25f * c1;
        float a2 = p2 * 0.25f * c2;
        float a3 = p3 * 0.25f * c3;

        acc.x = fmaf(a0, v0.x, fmaf(a1, v1.x, fmaf(a2, v2.x, fmaf(a3, v3.x, acc.x))));
        acc.y = fmaf(a0, v0.y, fmaf(a1, v1.y, fmaf(a2, v2.y, fmaf(a3, v3.y, acc.y))));
        acc.z = fmaf(a0, v0.z, fmaf(a1, v1.z, fmaf(a2, v2.z, fmaf(a3, v3.z, acc.z))));
        acc.w = fmaf(a0, v0.w, fmaf(a1, v1.w, fmaf(a2, v2.w, fmaf(a3, v3.w, acc.w))));
    }
    for (; p < e_end; p++) {
        int2 es0 = g_es[p];
        float4 k0 = *(const float4*)&g_k[(size_t)es0.y * HID + 4 * l];
        float4 v0 = *(const float4*)&g_v[(size_t)es0.y * HID + 4 * l];
        float4 w0 = __ldcs((const float4*)&w_ij[(size_t)es0.x * HID + 4 * l]);
        float p0 = q.x * w0.x * k0.x + q.y * w0.y * k0.y + q.z * w0.z * k0.z + q.w * w0.w * k0.w;
        p0 += __shfl_xor_sync(0xffffffffu, p0, 1);
        p0 += __shfl_xor_sync(0xffffffffu, p0, 2);
        float a0 = p0 * 0.25f * __ldg(&cutoff[es0.x]);
        acc.x = fmaf(a0, v0.x, acc.x);
        acc.y = fmaf(a0, v0.y, acc.y);
        acc.z = fmaf(a0, v0.z, acc.z);
        acc.w = fmaf(a0, v0.w, acc.w);
    }

    __stcs((float4*)&out[(size_t)node * HID + 4 * l], acc);
}

// ---------------------------------------------------------------------------
extern "C" void kernel_launch(void* const* d_in, const int* in_sizes, int n_in,
                              void* d_out, int out_size) {
    const float* x      = (const float*)d_in[0];
    const float* w_ij   = (const float*)d_in[1];
    const unsigned int* ei = (const unsigned int*)d_in[2];
    const float* cutoff = (const float*)d_in[3];
    const float* Wq     = (const float*)d_in[4];
    const float* Wk     = (const float*)d_in[5];
    const float* Wv     = (const float*)d_in[6];
    float* out = (float*)d_out;

    static cudaStream_t s2 = nullptr;
    static cudaEvent_t evFork = nullptr, evSort = nullptr;
    static bool use_streams = false;
    if (!s2 && !evFork) {
        bool ok = (cudaStreamCreateWithFlags(&s2, cudaStreamNonBlocking) == cudaSuccess)
               && (cudaEventCreateWithFlags(&evFork, cudaEventDisableTiming) == cudaSuccess)
               && (cudaEventCreateWithFlags(&evSort, cudaEventDisableTiming) == cudaSuccess);
        use_streams = ok;
    }

    int gx = (NN + TILE_N - 1) / TILE_N;
    int fused_blocks = (NN * 32 + 255) / 256;   // warp per node

    if (use_streams) {
        cudaEventRecord(evFork, 0);
        cudaStreamWaitEvent(s2, evFork, 0);

        // s2: sort chain (hidden under the GEMM chain on main)
        zero_and_detect<<<148, 256, 0, s2>>>(ei);
        convert_idx<<<148, 256, 0, s2>>>(ei);
        scan_phase1<<<NBLK, SCAN_B, 0, s2>>>();
        scan_phase2<<<1, 64, 0, s2>>>();
        scan_phase3<<<NBLK, SCAN_B, 0, s2>>>();
        permute_idx<<<148, 256, 0, s2>>>();
        cudaEventRecord(evSort, s2);

        // main: transpose -> full QKV GEMM
        transpose_w<<<48, 256>>>(Wq, Wk, Wv);
        dim3 g3(gx, 3);
        qkv_gemm<<<g3, 256>>>(x, 0);

        // join: fused edge needs sort + qkv
        cudaStreamWaitEvent(0, evSort, 0);
        edge_fused<<<fused_blocks, 256>>>(w_ij, cutoff, out);
    } else {
        zero_and_detect<<<148, 256>>>(ei);
        convert_idx<<<148, 256>>>(ei);
        scan_phase1<<<NBLK, SCAN_B>>>();
        scan_phase2<<<1, 64>>>();
        scan_phase3<<<NBLK, SCAN_B>>>();
        permute_idx<<<148, 256>>>();
        transpose_w<<<48, 256>>>(Wq, Wk, Wv);
        dim3 g3(gx, 3);
        qkv_gemm<<<g3, 256>>>(x, 0);
        edge_fused<<<fused_blocks, 256>>>(w_ij, cutoff, out);
    }
}

// round 13
// speedup vs baseline: 1.3814x; 1.3814x over previous
#include <cuda_runtime.h>

#define NN 50000
#define NE 600000
#define HID 128
#define TILE_N 64
#define KCH 32
#define SCAN_B 1024
#define NBLK ((NN + SCAN_B - 1) / SCAN_B)   // 49 scan blocks

typedef unsigned long long u64;

// Scratch (static device globals — no runtime allocation).
__device__ __align__(256) float g_q[(size_t)NN * HID];
__device__ __align__(256) float g_k[(size_t)NN * HID];
__device__ __align__(256) float g_v[(size_t)NN * HID];
__device__ __align__(256) float g_WT[3 * HID * HID];
__device__ __align__(256) int   g_src[NE];
__device__ __align__(256) int   g_dst[NE];
__device__ __align__(256) int   g_count[NN];
__device__ __align__(256) int   g_start[NN + 1];
__device__ __align__(256) int   g_cursor[NN];
__device__ __align__(256) int2  g_es[NE];        // (edge id, src) sorted by dst
__device__ __align__(256) int   g_bsum[NBLK];
__device__ __align__(256) int   g_boff[NBLK];
__device__ int g_is_i32;

// ---------------------------------------------------------------------------
// f32x2 packed-FMA helpers (FFMA2 — PTX-only, exact fp32).
// ---------------------------------------------------------------------------
__device__ __forceinline__ u64 pack2(float lo, float hi) {
    u64 r; asm("mov.b64 %0, {%1, %2};" : "=l"(r) : "f"(lo), "f"(hi)); return r;
}
__device__ __forceinline__ void fma2(u64& acc, u64 a, u64 b) {
    asm("fma.rn.f32x2 %0, %1, %2, %0;" : "+l"(acc) : "l"(a), "l"(b));
}

// ---------------------------------------------------------------------------
// Kernel Z: zero counters + dtype flag + detection in one pass.
// ---------------------------------------------------------------------------
__global__ void zero_and_detect(const unsigned int* __restrict__ ei_words) {
    int t = blockIdx.x * blockDim.x + threadIdx.x;
    if (t == 0) g_is_i32 = 0;
    for (int i = t; i < NN; i += blockDim.x * gridDim.x) g_count[i] = 0;
    unsigned int acc = 0;
    for (int i = t; i < NE; i += blockDim.x * gridDim.x)
        acc |= ei_words[2 * i + 1];
    if (acc) atomicOr(&g_is_i32, 1);
}

// ---------------------------------------------------------------------------
// Kernel B: decode edge_index into g_src/g_dst AND histogram dst degrees.
// ---------------------------------------------------------------------------
__global__ void convert_idx(const unsigned int* __restrict__ ei_words) {
    int t = blockIdx.x * blockDim.x + threadIdx.x;
    int i32 = g_is_i32;
    for (int e = t; e < NE; e += blockDim.x * gridDim.x) {
        int s, d;
        if (i32) {
            s = (int)ei_words[e];
            d = (int)ei_words[NE + e];
        } else {
            s = (int)ei_words[2 * (size_t)e];
            d = (int)ei_words[2 * ((size_t)NE + e)];
        }
        g_src[e] = s;
        g_dst[e] = d;
        atomicAdd(&g_count[d], 1);
    }
}

// ---------------------------------------------------------------------------
// 3-phase parallel scan.
// ---------------------------------------------------------------------------
__global__ __launch_bounds__(SCAN_B) void scan_phase1() {
    __shared__ int ps[SCAN_B];
    int tid = threadIdx.x;
    int idx = blockIdx.x * SCAN_B + tid;
    int val = (idx < NN) ? g_count[idx] : 0;
    ps[tid] = val;
    __syncthreads();
#pragma unroll
    for (int d = 1; d < SCAN_B; d <<= 1) {
        int v = (tid >= d) ? ps[tid - d] : 0;
        __syncthreads();
        ps[tid] += v;
        __syncthreads();
    }
    if (idx < NN) g_start[idx] = ps[tid] - val;
    if (tid == SCAN_B - 1) g_bsum[blockIdx.x] = ps[tid];
}

__global__ void scan_phase2() {
    int l = threadIdx.x;             // 64 threads, NBLK=49 <= 64
    int v = (l < NBLK) ? g_bsum[l] : 0;
    int orig = v;
    __shared__ int s[64];
    s[l] = v;
    __syncthreads();
#pragma unroll
    for (int d = 1; d < 64; d <<= 1) {
        int t = (l >= d) ? s[l - d] : 0;
        __syncthreads();
        s[l] += t;
        __syncthreads();
    }
    if (l < NBLK) g_boff[l] = s[l] - orig;
    if (l == 63) g_start[NN] = s[63];
}

__global__ __launch_bounds__(SCAN_B) void scan_phase3() {
    int idx = blockIdx.x * SCAN_B + threadIdx.x;
    if (idx < NN) {
        int v = g_start[idx] + g_boff[blockIdx.x];
        g_start[idx] = v;
        g_cursor[idx] = v;
    }
}

// ---------------------------------------------------------------------------
// Kernel D: permute (edge id, src) pairs into dst-sorted order.
// ---------------------------------------------------------------------------
__global__ void permute_idx() {
    int t = blockIdx.x * blockDim.x + threadIdx.x;
    for (int e = t; e < NE; e += blockDim.x * gridDim.x) {
        int d = g_dst[e];
        int pos = atomicAdd(&g_cursor[d], 1);
        g_es[pos] = make_int2(e, g_src[e]);
    }
}

// ---------------------------------------------------------------------------
// Kernel 0: transpose the three 128x128 weight matrices (tiny).
// ---------------------------------------------------------------------------
__global__ void transpose_w(const float* __restrict__ Wq,
                            const float* __restrict__ Wk,
                            const float* __restrict__ Wv) {
    int t = blockIdx.x * blockDim.x + threadIdx.x;
    int total = 3 * HID * HID;
    for (int idx = t; idx < total; idx += blockDim.x * gridDim.x) {
        int m = idx / (HID * HID);
        int r = idx - m * (HID * HID);
        int o = r >> 7;
        int d = r & 127;
        const float* W = (m == 0) ? Wq : (m == 1) ? Wk : Wv;
        g_WT[m * HID * HID + d * HID + o] = W[o * HID + d];
    }
}

// ---------------------------------------------------------------------------
// Kernel 1: QKV GEMM (FFMA2, R11 version — measured best), 3 CTAs/SM.
// ---------------------------------------------------------------------------
__global__ __launch_bounds__(256, 3) void qkv_gemm(const float* __restrict__ x,
                                                   int m_base) {
    __shared__ float wt[KCH][HID];
    __shared__ float xs[TILE_N][KCH];

    int m = blockIdx.y + m_base;
    const float* wtg = &g_WT[m * HID * HID];
    float* out = (m == 0) ? g_q : (m == 1) ? g_k : g_v;

    int node0 = blockIdx.x * TILE_N;
    int tid = threadIdx.x;
    int w = tid >> 5;
    int l = tid & 31;

    const float4* xg4 = (const float4*)x;
    int xn0 = tid >> 3,         xc0 = tid & 7;
    int xn1 = (tid + 256) >> 3, xc1 = (tid + 256) & 7;
    int gn0 = node0 + xn0, gn1 = node0 + xn1;

    u64 cxy[8], czw[8];
#pragma unroll
    for (int n = 0; n < 8; n++) { cxy[n] = 0ull; czw[n] = 0ull; }

#pragma unroll
    for (int kk = 0; kk < HID / KCH; kk++) {
        int k0 = kk * KCH;
        if (kk) __syncthreads();
        {
            float4* wt4 = (float4*)&wt[0][0];
            const float4* srcw = (const float4*)&wtg[(size_t)k0 * HID];
#pragma unroll
            for (int i = 0; i < 4; i++)
                wt4[tid + i * 256] = srcw[tid + i * 256];
        }
        {
            float4* xs4 = (float4*)&xs[0][0];
            xs4[tid] = (gn0 < NN) ? xg4[(size_t)gn0 * 32 + (k0 >> 2) + xc0]
                                  : make_float4(0.f, 0.f, 0.f, 0.f);
            xs4[tid + 256] = (gn1 < NN) ? xg4[(size_t)gn1 * 32 + (k0 >> 2) + xc1]
                                        : make_float4(0.f, 0.f, 0.f, 0.f);
        }
        __syncthreads();

#pragma unroll
        for (int d4 = 0; d4 < KCH / 4; d4++) {
            int d = d4 * 4;
            ulonglong2 w0 = *(ulonglong2*)&wt[d + 0][4 * l];
            ulonglong2 w1 = *(ulonglong2*)&wt[d + 1][4 * l];
            ulonglong2 w2 = *(ulonglong2*)&wt[d + 2][4 * l];
            ulonglong2 w3 = *(ulonglong2*)&wt[d + 3][4 * l];
#pragma unroll
            for (int n = 0; n < 8; n++) {
                float4 xv = *(float4*)&xs[8 * w + n][d];
                u64 xb0 = pack2(xv.x, xv.x);
                u64 xb1 = pack2(xv.y, xv.y);
                u64 xb2 = pack2(xv.z, xv.z);
                u64 xb3 = pack2(xv.w, xv.w);
                fma2(cxy[n], xb0, w0.x); fma2(czw[n], xb0, w0.y);
                fma2(cxy[n], xb1, w1.x); fma2(czw[n], xb1, w1.y);
                fma2(cxy[n], xb2, w2.x); fma2(czw[n], xb2, w2.y);
                fma2(cxy[n], xb3, w3.x); fma2(czw[n], xb3, w3.y);
            }
        }
    }

#pragma unroll
    for (int n = 0; n < 8; n++) {
        int gn = node0 + 8 * w + n;
        if (gn < NN) {
            ulonglong2 o2;
            o2.x = cxy[n];
            o2.y = czw[n];
            *(ulonglong2*)&out[(size_t)gn * HID + 4 * l] = o2;
        }
    }
}

// ---------------------------------------------------------------------------
// Kernel 2: FUSED dst-sorted edge kernel — ONE WARP = ONE CTA = ONE NODE.
// 32-thread CTAs retire as soon as their node finishes: zero intra-CTA
// degree imbalance (Poisson-degree max-of-8 waste with 256-thread CTAs).
// q loaded once per node; per edge k,v gathers (L2-resident) + coalesced
// w_ij row (__ldcs) + cutoff. Unroll 4 -> 12 LDG.128 in flight.
// ---------------------------------------------------------------------------
__global__ __launch_bounds__(32) void edge_fused(
    const float* __restrict__ w_ij,
    const float* __restrict__ cutoff,
    float* __restrict__ out) {

    int node = blockIdx.x;
    int l = threadIdx.x;

    int p     = g_start[node];
    int e_end = g_start[node + 1];

    float4 q = *(const float4*)&g_q[(size_t)node * HID + 4 * l];
    float4 acc = make_float4(0.f, 0.f, 0.f, 0.f);

    for (; p + 4 <= e_end; p += 4) {
        int2 es0 = g_es[p];
        int2 es1 = g_es[p + 1];
        int2 es2 = g_es[p + 2];
        int2 es3 = g_es[p + 3];

        float4 k0 = *(const float4*)&g_k[(size_t)es0.y * HID + 4 * l];
        float4 k1 = *(const float4*)&g_k[(size_t)es1.y * HID + 4 * l];
        float4 k2 = *(const float4*)&g_k[(size_t)es2.y * HID + 4 * l];
        float4 k3 = *(const float4*)&g_k[(size_t)es3.y * HID + 4 * l];
        float4 v0 = *(const float4*)&g_v[(size_t)es0.y * HID + 4 * l];
        float4 v1 = *(const float4*)&g_v[(size_t)es1.y * HID + 4 * l];
        float4 v2 = *(const float4*)&g_v[(size_t)es2.y * HID + 4 * l];
        float4 v3 = *(const float4*)&g_v[(size_t)es3.y * HID + 4 * l];
        float4 w0 = __ldcs((const float4*)&w_ij[(size_t)es0.x * HID + 4 * l]);
        float4 w1 = __ldcs((const float4*)&w_ij[(size_t)es1.x * HID + 4 * l]);
        float4 w2 = __ldcs((const float4*)&w_ij[(size_t)es2.x * HID + 4 * l]);
        float4 w3 = __ldcs((const float4*)&w_ij[(size_t)es3.x * HID + 4 * l]);
        float  c0 = __ldg(&cutoff[es0.x]);
        float  c1 = __ldg(&cutoff[es1.x]);
        float  c2 = __ldg(&cutoff[es2.x]);
        float  c3 = __ldg(&cutoff[es3.x]);

        float p0 = q.x * w0.x * k0.x + q.y * w0.y * k0.y + q.z * w0.z * k0.z + q.w * w0.w * k0.w;
        float p1 = q.x * w1.x * k1.x + q.y * w1.y * k1.y + q.z * w1.z * k1.z + q.w * w1.w * k1.w;
        float p2 = q.x * w2.x * k2.x + q.y * w2.y * k2.y + q.z * w2.z * k2.z + q.w * w2.w * k2.w;
        float p3 = q.x * w3.x * k3.x + q.y * w3.y * k3.y + q.z * w3.z * k3.z + q.w * w3.w * k3.w;

        p0 += __shfl_xor_sync(0xffffffffu, p0, 1);
        p0 += __shfl_xor_sync(0xffffffffu, p0, 2);
        p1 += __shfl_xor_sync(0xffffffffu, p1, 1);
        p1 += __shfl_xor_sync(0xffffffffu, p1, 2);
        p2 += __shfl_xor_sync(0xffffffffu, p2, 1);
        p2 += __shfl_xor_sync(0xffffffffu, p2, 2);
        p3 += __shfl_xor_sync(0xffffffffu, p3, 1);
        p3 += __shfl_xor_sync(0xffffffffu, p3, 2);

        float a0 = p0 * 0.25f * c0;
        float a1 = p1 * 0.25f * c1;
        float a2 = p2 * 0.25f * c2;
        float a3 = p3 * 0.25f * c3;

        acc.x = fmaf(a0, v0.x, fmaf(a1, v1.x, fmaf(a2, v2.x, fmaf(a3, v3.x, acc.x))));
        acc.y = fmaf(a0, v0.y, fmaf(a1, v1.y, fmaf(a2, v2.y, fmaf(a3, v3.y, acc.y))));
        acc.z = fmaf(a0, v0.z, fmaf(a1, v1.z, fmaf(a2, v2.z, fmaf(a3, v3.z, acc.z))));
        acc.w = fmaf(a0, v0.w, fmaf(a1, v1.w, fmaf(a2, v2.w, fmaf(a3, v3.w, acc.w))));
    }
    for (; p < e_end; p++) {
        int2 es0 = g_es[p];
        float4 k0 = *(const float4*)&g_k[(size_t)es0.y * HID + 4 * l];
        float4 v0 = *(const float4*)&g_v[(size_t)es0.y * HID + 4 * l];
        float4 w0 = __ldcs((const float4*)&w_ij[(size_t)es0.x * HID + 4 * l]);
        float p0 = q.x * w0.x * k0.x + q.y * w0.y * k0.y + q.z * w0.z * k0.z + q.w * w0.w * k0.w;
        p0 += __shfl_xor_sync(0xffffffffu, p0, 1);
        p0 += __shfl_xor_sync(0xffffffffu, p0, 2);
        float a0 = p0 * 0.25f * __ldg(&cutoff[es0.x]);
        acc.x = fmaf(a0, v0.x, acc.x);
        acc.y = fmaf(a0, v0.y, acc.y);
        acc.z = fmaf(a0, v0.z, acc.z);
        acc.w = fmaf(a0, v0.w, acc.w);
    }

    __stcs((float4*)&out[(size_t)node * HID + 4 * l], acc);
}

// ---------------------------------------------------------------------------
extern "C" void kernel_launch(void* const* d_in, const int* in_sizes, int n_in,
                              void* d_out, int out_size) {
    const float* x      = (const float*)d_in[0];
    const float* w_ij   = (const float*)d_in[1];
    const unsigned int* ei = (const unsigned int*)d_in[2];
    const float* cutoff = (const float*)d_in[3];
    const float* Wq     = (const float*)d_in[4];
    const float* Wk     = (const float*)d_in[5];
    const float* Wv     = (const float*)d_in[6];
    float* out = (float*)d_out;

    static cudaStream_t s2 = nullptr;
    static cudaEvent_t evFork = nullptr, evSort = nullptr;
    static bool use_streams = false;
    if (!s2 && !evFork) {
        bool ok = (cudaStreamCreateWithFlags(&s2, cudaStreamNonBlocking) == cudaSuccess)
               && (cudaEventCreateWithFlags(&evFork, cudaEventDisableTiming) == cudaSuccess)
               && (cudaEventCreateWithFlags(&evSort, cudaEventDisableTiming) == cudaSuccess);
        use_streams = ok;
    }

    int gx = (NN + TILE_N - 1) / TILE_N;

    if (use_streams) {
        cudaEventRecord(evFork, 0);
        cudaStreamWaitEvent(s2, evFork, 0);

        // s2: sort chain (hidden under the GEMM chain on main)
        zero_and_detect<<<148, 256, 0, s2>>>(ei);
        convert_idx<<<148, 256, 0, s2>>>(ei);
        scan_phase1<<<NBLK, SCAN_B, 0, s2>>>();
        scan_phase2<<<1, 64, 0, s2>>>();
        scan_phase3<<<NBLK, SCAN_B, 0, s2>>>();
        permute_idx<<<148, 256, 0, s2>>>();
        cudaEventRecord(evSort, s2);

        // main: transpose -> full QKV GEMM
        transpose_w<<<48, 256>>>(Wq, Wk, Wv);
        dim3 g3(gx, 3);
        qkv_gemm<<<g3, 256>>>(x, 0);

        // join: fused edge needs sort + qkv
        cudaStreamWaitEvent(0, evSort, 0);
        edge_fused<<<NN, 32>>>(w_ij, cutoff, out);
    } else {
        zero_and_detect<<<148, 256>>>(ei);
        convert_idx<<<148, 256>>>(ei);
        scan_phase1<<<NBLK, SCAN_B>>>();
        scan_phase2<<<1, 64>>>();
        scan_phase3<<<NBLK, SCAN_B>>>();
        permute_idx<<<148, 256>>>();
        transpose_w<<<48, 256>>>(Wq, Wk, Wv);
        dim3 g3(gx, 3);
        qkv_gemm<<<g3, 256>>>(x, 0);
        edge_fused<<<NN, 32>>>(w_ij, cutoff, out);
    }
}